// round 14
// baseline (speedup 1.0000x reference)
#include <cuda_runtime.h>
#include <cuda_fp16.h>
#include <cuda_bf16.h>

#define BB 256
#define SS 2048
#define EE 64
#define HH 128
#define G4 512   // 4*H

// x_proj scratch, GATE-INTERLEAVED, PRE-BIASED (b_u + b_all folded in):
// [(s*BB+b)*128 + c]*4 + g   (1.07 GB fp32)
__device__ float g_xp[(size_t)SS * BB * G4];

// ---- fast activations via MUFU.TANH ----------------------------------------
__device__ __forceinline__ float tanh_ap(float x) {
    float r;
    asm("tanh.approx.f32 %0, %1;" : "=f"(r) : "f"(x));
    return r;
}
__device__ __forceinline__ float sigm_f(float x) {
    return fmaf(0.5f, tanh_ap(0.5f * x), 0.5f);
}
__device__ __forceinline__ float tanh_f(float x) {
    return tanh_ap(x);
}

// ---- f32x2 packed-math helpers (sm_103a) ------------------------------------
typedef unsigned long long ull;

__device__ __forceinline__ ull fma2(ull a, ull b, ull c) {
    ull d;
    asm("fma.rn.f32x2 %0, %1, %2, %3;" : "=l"(d) : "l"(a), "l"(b), "l"(c));
    return d;
}
// bf16x2 (lo half = v_k, hi half = v_{k+1}) -> f32x2 (v_k, v_{k+1})
__device__ __forceinline__ ull bf2f2(unsigned int w) {
    unsigned int lo = w << 16;
    unsigned int hi = w & 0xFFFF0000u;
    ull r;
    asm("mov.b64 %0, {%1, %2};" : "=l"(r) : "r"(lo), "r"(hi));
    return r;
}
__device__ __forceinline__ float hsum2(ull v) {
    float x, y;
    asm("mov.b64 {%0, %1}, %2;" : "=f"(x), "=f"(y) : "l"(v));
    return x + y;
}
__device__ __forceinline__ unsigned int f2bf2(float hi, float lo) {
    unsigned int r;
    asm("cvt.rn.satfinite.bf16x2.f32 %0, %1, %2;" : "=r"(r) : "f"(hi), "f"(lo));
    return r;
}
__device__ __forceinline__ ull dup2(float x) {
    ull r;
    asm("mov.b64 %0, {%1, %1};" : "=l"(r) : "f"(x));
    return r;
}

// ---------------------------------------------------------------------------
// Kernel 1: x_proj = inputs @ U_all^T + (b_u + b_all)  (gate-interleaved,
// coalesced STG.128). BIG TILE: 128 b x 256 f (64 c x 4 g) per CTA, 8 steps.
// uT (64 KB) loaded once per CTA; inputs re-read only 2x chip-wide.
// Thread: cl = tid&63 (one column, 4 gates), bq = tid>>6 (32 b-rows).
// grid (2 c-blocks, 2 b-blocks, 256 s-blocks), 256 threads, ~100 KB SMEM.
// ---------------------------------------------------------------------------
__global__ __launch_bounds__(256) void xproj_kernel(
    const float* __restrict__ inputs,   // [B][S][E]
    const float* __restrict__ U_all,    // [4H][E]
    const float* __restrict__ b_u,      // [4H]
    const float* __restrict__ b_all)    // [4H]
{
    __shared__ float xT[64 * 132];   // [e][b], pitch 132 (33.8 KB)
    __shared__ float uT[64 * 256];   // [e][j], j = cl*4 + g (64 KB)

    const int s0     = blockIdx.z * 8;
    const int b_base = blockIdx.y * 128;
    const int c_base = blockIdx.x * 64;
    const int tid    = threadIdx.x;
    const int e      = tid & 63;
    const int r0     = tid >> 6;     // 0..3

    // U tile: load once. j = cl*4 + g  ->  f = g*128 + c_base + cl
    for (int idx = tid; idx < 64 * 256; idx += 256) {
        int j  = idx & 255;
        int ee = idx >> 8;
        int f  = (j & 3) * 128 + c_base + (j >> 2);
        uT[ee * 256 + j] = U_all[(size_t)f * EE + ee];
    }

    const int cl = tid & 63;         // column within c-block
    const int bq = tid >> 6;         // 0..3 : owns b rows bq*32..bq*32+31

    float4 bu;
    {
        float bv[4];
        #pragma unroll
        for (int u = 0; u < 4; u++) {
            int f = u * 128 + c_base + cl;
            bv[u] = b_u[f] + b_all[f];
        }
        bu = make_float4(bv[0], bv[1], bv[2], bv[3]);
    }

    for (int si = 0; si < 8; si++) {
        const int s = s0 + si;
        __syncthreads();   // protect xT reuse (and first-iter uT visibility)
        #pragma unroll
        for (int i = 0; i < 32; i++) {
            int b = r0 + i * 4;      // 0..127
            xT[e * 132 + b] = inputs[((size_t)(b_base + b) * SS + s) * EE + e];
        }
        __syncthreads();

        ull acc[32][2];
        #pragma unroll
        for (int i = 0; i < 32; i++) { acc[i][0] = 0ULL; acc[i][1] = 0ULL; }

        #pragma unroll 2
        for (int k = 0; k < 64; k++) {
            const float* xrow = &xT[k * 132 + bq * 32];
            float xa[32];
            #pragma unroll
            for (int q = 0; q < 8; q++) {
                float4 xv = *reinterpret_cast<const float4*>(&xrow[q * 4]);
                xa[q * 4 + 0] = xv.x; xa[q * 4 + 1] = xv.y;
                xa[q * 4 + 2] = xv.z; xa[q * 4 + 3] = xv.w;
            }
            ulonglong2 uvp = *reinterpret_cast<const ulonglong2*>(&uT[k * 256 + cl * 4]);
            #pragma unroll
            for (int i = 0; i < 32; i++) {
                ull xx = dup2(xa[i]);
                acc[i][0] = fma2(xx, uvp.x, acc[i][0]);
                acc[i][1] = fma2(xx, uvp.y, acc[i][1]);
            }
        }

        #pragma unroll
        for (int i = 0; i < 32; i++) {
            const int b = b_base + bq * 32 + i;
            float av[4];
            asm("mov.b64 {%0, %1}, %2;" : "=f"(av[0]), "=f"(av[1]) : "l"(acc[i][0]));
            asm("mov.b64 {%0, %1}, %2;" : "=f"(av[2]), "=f"(av[3]) : "l"(acc[i][1]));
            float4 v;
            v.x = av[0] + bu.x;
            v.y = av[1] + bu.y;
            v.z = av[2] + bu.z;
            v.w = av[3] + bu.w;
            *reinterpret_cast<float4*>(
                &g_xp[(((size_t)s * BB + b) * 128 + c_base + cl) * 4]) = v;
        }
    }
}

// ---------------------------------------------------------------------------
// Kernel 2: scan (R13, UNCHANGED). 128 CTAs x 512 threads, 2 batch rows/CTA.
// ---------------------------------------------------------------------------
#define SM_WG     0                      // 64*512 words = 131072 B
#define SM_HF     131072                 // 2*128 floats =   1024 B
#define SM_C      132096                 // 2*128 floats =   1024 B
#define SM_PREG   133120                 // 4*4*2*128 f  =  16384 B
#define SM_CPART  149504                 // 4*2*128 f    =   4096 B
#define SM_RED    153600                 // 256 floats   =   1024 B
#define SMEM_BYTES 154624

__global__ __launch_bounds__(512, 1) void scan_kernel(
    const float* __restrict__ TI,      // [B][S]
    const float* __restrict__ W_all,   // [4H][H]
    const float* __restrict__ W_d,     // [H][H]
    const float* __restrict__ b_d,     // [H]
    const float* __restrict__ W_out,   // [1][H]
    const float* __restrict__ b_out,   // [1]
    float* __restrict__ out)           // [B]
{
    extern __shared__ char smem[];
    unsigned int* wg2 = reinterpret_cast<unsigned int*>(smem + SM_WG);
    float* hf   = reinterpret_cast<float*>(smem + SM_HF);    // [2][128] fp32
    float* cb   = reinterpret_cast<float*>(smem + SM_C);     // [2][128] fp32
    float* preg = reinterpret_cast<float*>(smem + SM_PREG);  // [(kq*4+g)*2+m][128]
    float* cpart= reinterpret_cast<float*>(smem + SM_CPART); // [kq*2+m][128]
    float* red  = reinterpret_cast<float*>(smem + SM_RED);

    const int t  = threadIdx.x;
    const int b0 = blockIdx.x * 2;
    const int c  = t & 127;
    const int kq = t >> 7;      // 0..3 (warp-uniform)

    // ---- one-time: pack gate weights into SMEM (conflict-free layout) ----
    for (int u = t; u < 64 * 512; u += 512) {
        int r = u >> 9, rem = u & 511;
        int cc = rem >> 2, gg = rem & 3;
        float2 wv = *reinterpret_cast<const float2*>(&W_all[(size_t)(gg * 128 + cc) * HH + 2 * r]);
        wg2[u] = f2bf2(wv.y, wv.x);
    }

    // ---- wd weights -> 16 registers (step-invariant) ----
    uint4 wdr[4];
    #pragma unroll
    for (int q = 0; q < 4; q++) {
        unsigned int w[4];
        #pragma unroll
        for (int u = 0; u < 4; u++) {
            int p = q * 4 + u;
            float2 wv = *reinterpret_cast<const float2*>(&W_d[(size_t)c * HH + kq * 32 + 2 * p]);
            w[u] = f2bf2(wv.y, wv.x);
        }
        wdr[q] = make_uint4(w[0], w[1], w[2], w[3]);
    }
    const unsigned int* wdw = reinterpret_cast<const unsigned int*>(wdr);

    if (t < 256) { hf[t] = 0.0f; cb[t] = 0.0f; }

    // phase-B constants (threads 0..255: m = t>>7 == kq, col = c)
    float bd_r = 0.0f, wout_r = 0.0f;
    if (t < 256) {
        bd_r = b_d[c];
        wout_r = W_out[c];
    }
    const float bo = b_out[0];

    __syncthreads();

    const uint4* wgt4 = reinterpret_cast<const uint4*>(wg2) + kq * 16 * 128 + c;
    const ulonglong2* h0v = reinterpret_cast<const ulonglong2*>(hf + kq * 32);
    const ulonglong2* h1v = reinterpret_cast<const ulonglong2*>(hf + 128 + kq * 32);
    const ulonglong2* c0v = reinterpret_cast<const ulonglong2*>(cb + kq * 32);
    const ulonglong2* c1v = reinterpret_cast<const ulonglong2*>(cb + 128 + kq * 32);

    float out_acc = 0.0f;
    float c_reg = 0.0f;   // carried cell state for gating thread (m = kq, c)

    for (int s = 0; s < SS; s++) {
        // prefetch phase-B globals (hidden under phase A): ONE LDG.128 for xp
        float4 xq = make_float4(0.f, 0.f, 0.f, 0.f);
        float ti = 0.0f;
        if (t < 256) {
            const int m = t >> 7;
            xq = *reinterpret_cast<const float4*>(
                &g_xp[(((size_t)s * BB + b0 + m) * 128 + c) * 4]);
            ti = TI[(size_t)(b0 + m) * SS + s];
        }

        // ---- Phase A: quarter-k partial dots (h fp32, no h decompress) ----
        ull acc0[4] = {0ULL, 0ULL, 0ULL, 0ULL};
        ull acc1[4] = {0ULL, 0ULL, 0ULL, 0ULL};
        ull d0 = 0ULL, d1 = 0ULL;

        #pragma unroll
        for (int j = 0; j < 4; j++) {          // each j: 4 k-pairs (8 k)
            ulonglong2 ha0 = h0v[2 * j];
            ulonglong2 hb0 = h0v[2 * j + 1];
            ulonglong2 ha1 = h1v[2 * j];
            ulonglong2 hb1 = h1v[2 * j + 1];
            ull hp0[4] = {ha0.x, ha0.y, hb0.x, hb0.y};
            ull hp1[4] = {ha1.x, ha1.y, hb1.x, hb1.y};
            #pragma unroll
            for (int p = 0; p < 4; p++) {      // k-pair index within j
                uint4 wv = wgt4[(j * 4 + p) * 128];
                const unsigned int* w = reinterpret_cast<const unsigned int*>(&wv);
                #pragma unroll
                for (int g = 0; g < 4; g++) {
                    ull wg_ = bf2f2(w[g]);
                    acc0[g] = fma2(hp0[p], wg_, acc0[g]);
                    acc1[g] = fma2(hp1[p], wg_, acc1[g]);
                }
            }
            // wd: 4 k-pairs of the c-state (fp32) against register weights
            ulonglong2 ca = c0v[2 * j], cbq = c0v[2 * j + 1];
            ulonglong2 da = c1v[2 * j], dbq = c1v[2 * j + 1];
            ull wdA = bf2f2(wdw[4 * j + 0]);
            ull wdB = bf2f2(wdw[4 * j + 1]);
            ull wdC = bf2f2(wdw[4 * j + 2]);
            ull wdD = bf2f2(wdw[4 * j + 3]);
            d0 = fma2(ca.x, wdA, d0);  d0 = fma2(ca.y, wdB, d0);
            d0 = fma2(cbq.x, wdC, d0); d0 = fma2(cbq.y, wdD, d0);
            d1 = fma2(da.x, wdA, d1);  d1 = fma2(da.y, wdB, d1);
            d1 = fma2(dbq.x, wdC, d1); d1 = fma2(dbq.y, wdD, d1);
        }

        // ---- partial stores (gating threads keep their OWN row in regs) ----
        float own[4], ownd = 0.0f;
        if (t < 128) {              // kq=0, gating m=0: keep row0, store row1
            #pragma unroll
            for (int g = 0; g < 4; g++) {
                own[g] = hsum2(acc0[g]);
                preg[((0 * 4 + g) * 2 + 1) * 128 + c] = hsum2(acc1[g]);
            }
            ownd = hsum2(d0);
            cpart[(0 * 2 + 1) * 128 + c] = hsum2(d1);
        } else if (t < 256) {       // kq=1, gating m=1: keep row1, store row0
            #pragma unroll
            for (int g = 0; g < 4; g++) {
                own[g] = hsum2(acc1[g]);
                preg[((1 * 4 + g) * 2 + 0) * 128 + c] = hsum2(acc0[g]);
            }
            ownd = hsum2(d1);
            cpart[(1 * 2 + 0) * 128 + c] = hsum2(d0);
        } else {                    // kq=2,3: store everything
            #pragma unroll
            for (int g = 0; g < 4; g++) {
                preg[((kq * 4 + g) * 2 + 0) * 128 + c] = hsum2(acc0[g]);
                preg[((kq * 4 + g) * 2 + 1) * 128 + c] = hsum2(acc1[g]);
            }
            cpart[(kq * 2 + 0) * 128 + c] = hsum2(d0);
            cpart[(kq * 2 + 1) * 128 + c] = hsum2(d1);
        }
        __syncthreads();

        // ---- Phase B: gating (threads 0..255; m = kq, col = c) ----
        if (t < 256) {
            const int m = t >> 7;
            const int ko = m ^ 1;   // the other low kq holding our row's partial
            const float xpv[4] = {xq.x, xq.y, xq.z, xq.w};
            float pg[4];
            #pragma unroll
            for (int g = 0; g < 4; g++) {
                pg[g] = own[g]
                      + preg[((ko * 4 + g) * 2 + m) * 128 + c]
                      + preg[((2  * 4 + g) * 2 + m) * 128 + c]
                      + preg[((3  * 4 + g) * 2 + m) * 128 + c]
                      + xpv[g];                    // bias pre-folded into xp
            }
            float fg = sigm_f(pg[0]);
            float ig = sigm_f(pg[1]);
            float og = sigm_f(pg[2]);
            float ct = sigm_f(pg[3]);
            float cp = ownd + cpart[(ko * 2 + m) * 128 + c]
                     + cpart[(2 * 2 + m) * 128 + c]
                     + cpart[(3 * 2 + m) * 128 + c] + bd_r;

            float cs1  = tanh_f(cp);
            float cadj = (c_reg - cs1) + cs1 * ti;
            float cnew = fg * cadj + ig * ct;
            float hnew = og * tanh_f(cnew);
            c_reg = cnew;

            cb[m * 128 + c] = cnew;   // fp32
            hf[m * 128 + c] = hnew;   // fp32 (broadcast reads are cheap)
            out_acc += hnew * wout_r;
        }
        __syncthreads();
    }

    // ---- out[b] = sum_s h_s @ W_out + S * b_out ----
    if (t < 256) red[t] = out_acc;
    __syncthreads();
    if (t == 0) {
        float s0 = 0.0f;
        for (int k = 0; k < 128; k++) s0 += red[k];
        out[b0] = s0 + (float)SS * bo;
    }
    if (t == 1) {
        float s1 = 0.0f;
        for (int k = 0; k < 128; k++) s1 += red[128 + k];
        out[b0 + 1] = s1 + (float)SS * bo;
    }
}

// ---------------------------------------------------------------------------
extern "C" void kernel_launch(void* const* d_in, const int* in_sizes, int n_in,
                              void* d_out, int out_size)
{
    const float* inputs = (const float*)d_in[0];
    const float* TI     = (const float*)d_in[1];
    const float* W_all  = (const float*)d_in[2];
    const float* b_all  = (const float*)d_in[3];
    const float* U_all  = (const float*)d_in[4];
    const float* b_u    = (const float*)d_in[5];
    const float* W_d    = (const float*)d_in[6];
    const float* b_d    = (const float*)d_in[7];
    const float* W_out  = (const float*)d_in[8];
    const float* b_out  = (const float*)d_in[9];
    float* out = (float*)d_out;

    xproj_kernel<<<dim3(2, 2, 256), 256>>>(inputs, U_all, b_u, b_all);

    cudaFuncSetAttribute(scan_kernel,
                         cudaFuncAttributeMaxDynamicSharedMemorySize, SMEM_BYTES);
    scan_kernel<<<128, 512, SMEM_BYTES>>>(TI, W_all, W_d, b_d,
                                          W_out, b_out, out);
}

// round 15
// speedup vs baseline: 1.0414x; 1.0414x over previous
#include <cuda_runtime.h>
#include <cuda_fp16.h>
#include <cuda_bf16.h>

#define BB 256
#define SS 2048
#define EE 64
#define HH 128
#define G4 512   // 4*H

// x_proj scratch, GATE-INTERLEAVED, PRE-BIASED (b_u + b_all folded in):
// [(s*BB+b)*128 + c]*4 + g   (1.07 GB fp32)
__device__ float g_xp[(size_t)SS * BB * G4];

// ---- fast activations via MUFU.TANH ----------------------------------------
__device__ __forceinline__ float tanh_ap(float x) {
    float r;
    asm("tanh.approx.f32 %0, %1;" : "=f"(r) : "f"(x));
    return r;
}
__device__ __forceinline__ float sigm_f(float x) {
    return fmaf(0.5f, tanh_ap(0.5f * x), 0.5f);
}
__device__ __forceinline__ float tanh_f(float x) {
    return tanh_ap(x);
}

// ---- f32x2 packed-math helpers (sm_103a) ------------------------------------
typedef unsigned long long ull;

__device__ __forceinline__ ull fma2(ull a, ull b, ull c) {
    ull d;
    asm("fma.rn.f32x2 %0, %1, %2, %3;" : "=l"(d) : "l"(a), "l"(b), "l"(c));
    return d;
}
// bf16x2 (lo half = v_k, hi half = v_{k+1}) -> f32x2 (v_k, v_{k+1})
__device__ __forceinline__ ull bf2f2(unsigned int w) {
    unsigned int lo = w << 16;
    unsigned int hi = w & 0xFFFF0000u;
    ull r;
    asm("mov.b64 %0, {%1, %2};" : "=l"(r) : "r"(lo), "r"(hi));
    return r;
}
__device__ __forceinline__ float hsum2(ull v) {
    float x, y;
    asm("mov.b64 {%0, %1}, %2;" : "=f"(x), "=f"(y) : "l"(v));
    return x + y;
}
__device__ __forceinline__ unsigned int f2bf2(float hi, float lo) {
    unsigned int r;
    asm("cvt.rn.satfinite.bf16x2.f32 %0, %1, %2;" : "=r"(r) : "f"(hi), "f"(lo));
    return r;
}
__device__ __forceinline__ ull dup2(float x) {
    ull r;
    asm("mov.b64 %0, {%1, %1};" : "=l"(r) : "f"(x));
    return r;
}

// ---------------------------------------------------------------------------
// Kernel 1: x_proj = inputs @ U_all^T + (b_u + b_all)  (gate-interleaved,
// coalesced STG.128). R13 tile (16 c x 4 g, 128 b, 8 steps/CTA) but the
// inner product is PACKED OVER b: x pairs come straight out of LDS.128
// (consecutive b), only the 4 U scalars are duplicated per k.
// Thread: cl = tid&15 (one column, 4 gates), bq = tid>>4 (8 b-rows = 4 pairs).
// grid (8 c-blocks, 2 b-blocks, 256 s-blocks), 256 threads.
// ---------------------------------------------------------------------------
__global__ __launch_bounds__(256) void xproj_kernel(
    const float* __restrict__ inputs,   // [B][S][E]
    const float* __restrict__ U_all,    // [4H][E]
    const float* __restrict__ b_u,      // [4H]
    const float* __restrict__ b_all)    // [4H]
{
    __shared__ float xT[64 * 132];  // [e][b], pitch 132
    __shared__ float uT[64 * 68];   // [e][j]  j = cl*4 + g

    const int s0     = blockIdx.z * 8;
    const int b_base = blockIdx.y * 128;
    const int c_base = blockIdx.x * 16;
    const int tid    = threadIdx.x;
    const int e      = tid & 63;
    const int r0     = tid >> 6;    // 0..3

    // U tile: load once. j = cl*4 + g  ->  f = g*128 + c_base + cl
    #pragma unroll
    for (int i = 0; i < 16; i++) {
        int j = r0 + i * 4;
        int f = (j & 3) * 128 + c_base + (j >> 2);
        uT[e * 68 + j] = U_all[(size_t)f * EE + e];
    }

    const int cl = tid & 15;        // column within c-block
    const int bq = tid >> 4;        // 0..15 : owns b rows bq*8..bq*8+7

    float4 bu;
    {
        float bv[4];
        #pragma unroll
        for (int u = 0; u < 4; u++) {
            int f = u * 128 + c_base + cl;
            bv[u] = b_u[f] + b_all[f];
        }
        bu = make_float4(bv[0], bv[1], bv[2], bv[3]);
    }

    for (int si = 0; si < 8; si++) {
        const int s = s0 + si;
        __syncthreads();   // protect xT reuse (and first-iter uT visibility)
        #pragma unroll
        for (int i = 0; i < 32; i++) {
            int b = r0 + i * 4;    // 0..127
            xT[e * 132 + b] = inputs[((size_t)(b_base + b) * SS + s) * EE + e];
        }
        __syncthreads();

        // acc[bp][f]: f32x2 over batch pair bp (rows 2bp, 2bp+1), gate-value f
        ull acc[4][4];
        #pragma unroll
        for (int i = 0; i < 4; i++)
            #pragma unroll
            for (int f = 0; f < 4; f++) acc[i][f] = 0ULL;

        #pragma unroll 8
        for (int k = 0; k < 64; k++) {
            // 8 consecutive b as 4 ready f32x2 pairs (no dup needed)
            const ulonglong2* xp = reinterpret_cast<const ulonglong2*>(
                &xT[k * 132 + bq * 8]);
            ulonglong2 xv0 = xp[0];   // (b0,b1) (b2,b3)
            ulonglong2 xv1 = xp[1];   // (b4,b5) (b6,b7)
            ull xb[4] = {xv0.x, xv0.y, xv1.x, xv1.y};
            // 4 U scalars (this column's gates) -> dup to f32x2
            float4 uv = *reinterpret_cast<const float4*>(&uT[k * 68 + cl * 4]);
            ull ud[4] = {dup2(uv.x), dup2(uv.y), dup2(uv.z), dup2(uv.w)};
            #pragma unroll
            for (int i = 0; i < 4; i++) {
                #pragma unroll
                for (int f = 0; f < 4; f++)
                    acc[i][f] = fma2(xb[i], ud[f], acc[i][f]);
            }
        }

        // epilogue: unpack (b-pair, f) -> per-b float4 over gates, STG.128
        #pragma unroll
        for (int i = 0; i < 4; i++) {
            float lo[4], hi[4];
            #pragma unroll
            for (int f = 0; f < 4; f++) {
                asm("mov.b64 {%0, %1}, %2;"
                    : "=f"(lo[f]), "=f"(hi[f]) : "l"(acc[i][f]));
            }
            const int b_lo = b_base + bq * 8 + 2 * i;
            float4 v0, v1;
            v0.x = lo[0] + bu.x; v0.y = lo[1] + bu.y;
            v0.z = lo[2] + bu.z; v0.w = lo[3] + bu.w;
            v1.x = hi[0] + bu.x; v1.y = hi[1] + bu.y;
            v1.z = hi[2] + bu.z; v1.w = hi[3] + bu.w;
            *reinterpret_cast<float4*>(
                &g_xp[(((size_t)s * BB + b_lo) * 128 + c_base + cl) * 4]) = v0;
            *reinterpret_cast<float4*>(
                &g_xp[(((size_t)s * BB + b_lo + 1) * 128 + c_base + cl) * 4]) = v1;
        }
    }
}

// ---------------------------------------------------------------------------
// Kernel 2: scan (R13, UNCHANGED). 128 CTAs x 512 threads, 2 batch rows/CTA.
// ---------------------------------------------------------------------------
#define SM_WG     0                      // 64*512 words = 131072 B
#define SM_HF     131072                 // 2*128 floats =   1024 B
#define SM_C      132096                 // 2*128 floats =   1024 B
#define SM_PREG   133120                 // 4*4*2*128 f  =  16384 B
#define SM_CPART  149504                 // 4*2*128 f    =   4096 B
#define SM_RED    153600                 // 256 floats   =   1024 B
#define SMEM_BYTES 154624

__global__ __launch_bounds__(512, 1) void scan_kernel(
    const float* __restrict__ TI,      // [B][S]
    const float* __restrict__ W_all,   // [4H][H]
    const float* __restrict__ W_d,     // [H][H]
    const float* __restrict__ b_d,     // [H]
    const float* __restrict__ W_out,   // [1][H]
    const float* __restrict__ b_out,   // [1]
    float* __restrict__ out)           // [B]
{
    extern __shared__ char smem[];
    unsigned int* wg2 = reinterpret_cast<unsigned int*>(smem + SM_WG);
    float* hf   = reinterpret_cast<float*>(smem + SM_HF);    // [2][128] fp32
    float* cb   = reinterpret_cast<float*>(smem + SM_C);     // [2][128] fp32
    float* preg = reinterpret_cast<float*>(smem + SM_PREG);  // [(kq*4+g)*2+m][128]
    float* cpart= reinterpret_cast<float*>(smem + SM_CPART); // [kq*2+m][128]
    float* red  = reinterpret_cast<float*>(smem + SM_RED);

    const int t  = threadIdx.x;
    const int b0 = blockIdx.x * 2;
    const int c  = t & 127;
    const int kq = t >> 7;      // 0..3 (warp-uniform)

    // ---- one-time: pack gate weights into SMEM (conflict-free layout) ----
    for (int u = t; u < 64 * 512; u += 512) {
        int r = u >> 9, rem = u & 511;
        int cc = rem >> 2, gg = rem & 3;
        float2 wv = *reinterpret_cast<const float2*>(&W_all[(size_t)(gg * 128 + cc) * HH + 2 * r]);
        wg2[u] = f2bf2(wv.y, wv.x);
    }

    // ---- wd weights -> 16 registers (step-invariant) ----
    uint4 wdr[4];
    #pragma unroll
    for (int q = 0; q < 4; q++) {
        unsigned int w[4];
        #pragma unroll
        for (int u = 0; u < 4; u++) {
            int p = q * 4 + u;
            float2 wv = *reinterpret_cast<const float2*>(&W_d[(size_t)c * HH + kq * 32 + 2 * p]);
            w[u] = f2bf2(wv.y, wv.x);
        }
        wdr[q] = make_uint4(w[0], w[1], w[2], w[3]);
    }
    const unsigned int* wdw = reinterpret_cast<const unsigned int*>(wdr);

    if (t < 256) { hf[t] = 0.0f; cb[t] = 0.0f; }

    // phase-B constants (threads 0..255: m = t>>7 == kq, col = c)
    float bd_r = 0.0f, wout_r = 0.0f;
    if (t < 256) {
        bd_r = b_d[c];
        wout_r = W_out[c];
    }
    const float bo = b_out[0];

    __syncthreads();

    const uint4* wgt4 = reinterpret_cast<const uint4*>(wg2) + kq * 16 * 128 + c;
    const ulonglong2* h0v = reinterpret_cast<const ulonglong2*>(hf + kq * 32);
    const ulonglong2* h1v = reinterpret_cast<const ulonglong2*>(hf + 128 + kq * 32);
    const ulonglong2* c0v = reinterpret_cast<const ulonglong2*>(cb + kq * 32);
    const ulonglong2* c1v = reinterpret_cast<const ulonglong2*>(cb + 128 + kq * 32);

    float out_acc = 0.0f;
    float c_reg = 0.0f;   // carried cell state for gating thread (m = kq, c)

    for (int s = 0; s < SS; s++) {
        // prefetch phase-B globals (hidden under phase A): ONE LDG.128 for xp
        float4 xq = make_float4(0.f, 0.f, 0.f, 0.f);
        float ti = 0.0f;
        if (t < 256) {
            const int m = t >> 7;
            xq = *reinterpret_cast<const float4*>(
                &g_xp[(((size_t)s * BB + b0 + m) * 128 + c) * 4]);
            ti = TI[(size_t)(b0 + m) * SS + s];
        }

        // ---- Phase A: quarter-k partial dots (h fp32, no h decompress) ----
        ull acc0[4] = {0ULL, 0ULL, 0ULL, 0ULL};
        ull acc1[4] = {0ULL, 0ULL, 0ULL, 0ULL};
        ull d0 = 0ULL, d1 = 0ULL;

        #pragma unroll
        for (int j = 0; j < 4; j++) {          // each j: 4 k-pairs (8 k)
            ulonglong2 ha0 = h0v[2 * j];
            ulonglong2 hb0 = h0v[2 * j + 1];
            ulonglong2 ha1 = h1v[2 * j];
            ulonglong2 hb1 = h1v[2 * j + 1];
            ull hp0[4] = {ha0.x, ha0.y, hb0.x, hb0.y};
            ull hp1[4] = {ha1.x, ha1.y, hb1.x, hb1.y};
            #pragma unroll
            for (int p = 0; p < 4; p++) {      // k-pair index within j
                uint4 wv = wgt4[(j * 4 + p) * 128];
                const unsigned int* w = reinterpret_cast<const unsigned int*>(&wv);
                #pragma unroll
                for (int g = 0; g < 4; g++) {
                    ull wg_ = bf2f2(w[g]);
                    acc0[g] = fma2(hp0[p], wg_, acc0[g]);
                    acc1[g] = fma2(hp1[p], wg_, acc1[g]);
                }
            }
            // wd: 4 k-pairs of the c-state (fp32) against register weights
            ulonglong2 ca = c0v[2 * j], cbq = c0v[2 * j + 1];
            ulonglong2 da = c1v[2 * j], dbq = c1v[2 * j + 1];
            ull wdA = bf2f2(wdw[4 * j + 0]);
            ull wdB = bf2f2(wdw[4 * j + 1]);
            ull wdC = bf2f2(wdw[4 * j + 2]);
            ull wdD = bf2f2(wdw[4 * j + 3]);
            d0 = fma2(ca.x, wdA, d0);  d0 = fma2(ca.y, wdB, d0);
            d0 = fma2(cbq.x, wdC, d0); d0 = fma2(cbq.y, wdD, d0);
            d1 = fma2(da.x, wdA, d1);  d1 = fma2(da.y, wdB, d1);
            d1 = fma2(dbq.x, wdC, d1); d1 = fma2(dbq.y, wdD, d1);
        }

        // ---- partial stores (gating threads keep their OWN row in regs) ----
        float own[4], ownd = 0.0f;
        if (t < 128) {              // kq=0, gating m=0: keep row0, store row1
            #pragma unroll
            for (int g = 0; g < 4; g++) {
                own[g] = hsum2(acc0[g]);
                preg[((0 * 4 + g) * 2 + 1) * 128 + c] = hsum2(acc1[g]);
            }
            ownd = hsum2(d0);
            cpart[(0 * 2 + 1) * 128 + c] = hsum2(d1);
        } else if (t < 256) {       // kq=1, gating m=1: keep row1, store row0
            #pragma unroll
            for (int g = 0; g < 4; g++) {
                own[g] = hsum2(acc1[g]);
                preg[((1 * 4 + g) * 2 + 0) * 128 + c] = hsum2(acc0[g]);
            }
            ownd = hsum2(d1);
            cpart[(1 * 2 + 0) * 128 + c] = hsum2(d0);
        } else {                    // kq=2,3: store everything
            #pragma unroll
            for (int g = 0; g < 4; g++) {
                preg[((kq * 4 + g) * 2 + 0) * 128 + c] = hsum2(acc0[g]);
                preg[((kq * 4 + g) * 2 + 1) * 128 + c] = hsum2(acc1[g]);
            }
            cpart[(kq * 2 + 0) * 128 + c] = hsum2(d0);
            cpart[(kq * 2 + 1) * 128 + c] = hsum2(d1);
        }
        __syncthreads();

        // ---- Phase B: gating (threads 0..255; m = kq, col = c) ----
        if (t < 256) {
            const int m = t >> 7;
            const int ko = m ^ 1;   // the other low kq holding our row's partial
            const float xpv[4] = {xq.x, xq.y, xq.z, xq.w};
            float pg[4];
            #pragma unroll
            for (int g = 0; g < 4; g++) {
                pg[g] = own[g]
                      + preg[((ko * 4 + g) * 2 + m) * 128 + c]
                      + preg[((2  * 4 + g) * 2 + m) * 128 + c]
                      + preg[((3  * 4 + g) * 2 + m) * 128 + c]
                      + xpv[g];                    // bias pre-folded into xp
            }
            float fg = sigm_f(pg[0]);
            float ig = sigm_f(pg[1]);
            float og = sigm_f(pg[2]);
            float ct = sigm_f(pg[3]);
            float cp = ownd + cpart[(ko * 2 + m) * 128 + c]
                     + cpart[(2 * 2 + m) * 128 + c]
                     + cpart[(3 * 2 + m) * 128 + c] + bd_r;

            float cs1  = tanh_f(cp);
            float cadj = (c_reg - cs1) + cs1 * ti;
            float cnew = fg * cadj + ig * ct;
            float hnew = og * tanh_f(cnew);
            c_reg = cnew;

            cb[m * 128 + c] = cnew;   // fp32
            hf[m * 128 + c] = hnew;   // fp32 (broadcast reads are cheap)
            out_acc += hnew * wout_r;
        }
        __syncthreads();
    }

    // ---- out[b] = sum_s h_s @ W_out + S * b_out ----
    if (t < 256) red[t] = out_acc;
    __syncthreads();
    if (t == 0) {
        float s0 = 0.0f;
        for (int k = 0; k < 128; k++) s0 += red[k];
        out[b0] = s0 + (float)SS * bo;
    }
    if (t == 1) {
        float s1 = 0.0f;
        for (int k = 0; k < 128; k++) s1 += red[128 + k];
        out[b0 + 1] = s1 + (float)SS * bo;
    }
}

// ---------------------------------------------------------------------------
extern "C" void kernel_launch(void* const* d_in, const int* in_sizes, int n_in,
                              void* d_out, int out_size)
{
    const float* inputs = (const float*)d_in[0];
    const float* TI     = (const float*)d_in[1];
    const float* W_all  = (const float*)d_in[2];
    const float* b_all  = (const float*)d_in[3];
    const float* U_all  = (const float*)d_in[4];
    const float* b_u    = (const float*)d_in[5];
    const float* W_d    = (const float*)d_in[6];
    const float* b_d    = (const float*)d_in[7];
    const float* W_out  = (const float*)d_in[8];
    const float* b_out  = (const float*)d_in[9];
    float* out = (float*)d_out;

    xproj_kernel<<<dim3(8, 2, 256), 256>>>(inputs, U_all, b_u, b_all);

    cudaFuncSetAttribute(scan_kernel,
                         cudaFuncAttributeMaxDynamicSharedMemorySize, SMEM_BYTES);
    scan_kernel<<<128, 512, SMEM_BYTES>>>(TI, W_all, W_d, b_d,
                                          W_out, b_out, out);
}